// round 11
// baseline (speedup 1.0000x reference)
#include <cuda_runtime.h>
#include <math.h>

typedef unsigned long long ull;

// Shapes
#define NSEQ_C 8192            // B*W
#define T_CH   48              // chars per word
#define M_C    (NSEQ_C*T_CH)   // 393216 char rows
#define M_M    8192            // msg-level rows (B*W)

// ---------------- static device scratch (no allocations allowed) ----------------
__device__ float g_xg[301989888ull];        // [2][M][384] gate preacts
__device__ float g_out[100663296ull];       // [M][256] BiGRU outputs
__device__ float g_words[2097152ull];       // [8192][256] pooled word vectors / messages

// ---------------- helpers ----------------
__device__ __forceinline__ void ffma2(ull &d, ull a, ull b) {
    asm("fma.rn.f32x2 %0, %1, %2, %0;" : "+l"(d) : "l"(a), "l"(b));
}
__device__ __forceinline__ float f2sum(ull v) {
    unsigned lo, hi;
    asm("mov.b64 {%0,%1}, %2;" : "=r"(lo), "=r"(hi) : "l"(v));
    return __uint_as_float(lo) + __uint_as_float(hi);
}
__device__ __forceinline__ float sigmoidf_(float x) { return 1.0f / (1.0f + expf(-x)); }

// Load K=NU*4 floats of a weight row into packed-f32x2 registers (16B loads).
template <int NU>
__device__ __forceinline__ void loadW(ull* w2, const float* __restrict__ W) {
    const ulonglong2* wr = (const ulonglong2*)W;
#pragma unroll
    for (int j = 0; j < NU; j++) { ulonglong2 v = wr[j]; w2[2 * j] = v.x; w2[2 * j + 1] = v.y; }
}

// dot over NU*4 floats from shared (LDS.128, broadcast-friendly), 4 FFMA2 chains.
template <int NU>
__device__ __forceinline__ float dotT(const ull* w2, const float* xp) {
    const ulonglong2* xr = (const ulonglong2*)xp;
    ull a0 = 0, a1 = 0, a2 = 0, a3 = 0;
#pragma unroll
    for (int j = 0; j < NU; j += 2) {
        ulonglong2 v0 = xr[j];
        ulonglong2 v1 = xr[j + 1];
        ffma2(a0, w2[2 * j],     v0.x);
        ffma2(a1, w2[2 * j + 1], v0.y);
        ffma2(a2, w2[2 * j + 2], v1.x);
        ffma2(a3, w2[2 * j + 3], v1.y);
    }
    return (f2sum(a0) + f2sum(a1)) + (f2sum(a2) + f2sum(a3));
}

// ---------------- K1: char input gates, fused embedding gather (K=64) ----------------
// 256 threads, 1 column/thread, full K in 64 regs -> 2 blocks/SM (16 warps).
__global__ __launch_bounds__(256, 2)
void xg_char_kernel(const int* __restrict__ chars, const float* __restrict__ emb,
                    const float* __restrict__ WihF, const float* __restrict__ WihB,
                    const float* __restrict__ biF,  const float* __restrict__ biB)
{
    const int RB = 96;
    __shared__ __align__(16) float xs[RB][64];
    const int m0  = blockIdx.y * RB;
    const int tid = threadIdx.x;
    const int gcol = blockIdx.x * 256 + tid;      // 0..767
    const int dir  = gcol >= 384;
    const int row  = gcol - dir * 384;

    const float* W = dir ? WihB : WihF;
    ull w2[32];
    loadW<16>(w2, W + (size_t)row * 64);
    const float bias = (dir ? biB : biF)[row];

    float4* xs4 = (float4*)xs;
    const float4* emb4 = (const float4*)emb;
    for (int idx = tid; idx < RB * 16; idx += 256) {
        int r = idx >> 4, q = idx & 15;
        int ch = chars[m0 + r];
        xs4[idx] = emb4[(size_t)ch * 16 + q];
    }
    __syncthreads();

    float* outp = g_xg + (size_t)dir * M_C * 384 + (size_t)m0 * 384 + row;
#pragma unroll 2
    for (int r = 0; r < RB; r++) outp[(size_t)r * 384] = dotT<16>(w2, xs[r]) + bias;
}

// ---------------- K4: message input gates GEMM (K=256), 4-way k-split + shfl ----------------
__global__ __launch_bounds__(512, 1)
void xg_k256_kernel(const float* __restrict__ WihF, const float* __restrict__ WihB,
                    const float* __restrict__ biF,  const float* __restrict__ biB)
{
    const int RB = 16;
    __shared__ __align__(16) float xs[RB][256];
    __shared__ float ps[RB][128];
    const int colg = blockIdx.x;                 // 0..5 (6*128 cols, both dirs)
    const int m0   = blockIdx.y * RB;
    const int tid  = threadIdx.x;
    const int kq = tid & 3, c2 = tid >> 2;       // kq in lane bits 0-1
    const int gcol = colg * 128 + c2;
    const int dir  = gcol >= 384;
    const int row  = gcol - dir * 384;

    const float* W = dir ? WihB : WihF;
    ull w2[32];
    loadW<16>(w2, W + (size_t)row * 256 + kq * 64);

    float4* xs4 = (float4*)xs;
    const float4* X4 = (const float4*)(g_words + (size_t)m0 * 256);
    for (int i = tid; i < RB * 64; i += 512) xs4[i] = X4[i];
    __syncthreads();

#pragma unroll 2
    for (int r = 0; r < RB; r++) {
        float v = dotT<16>(w2, xs[r] + kq * 64);
        v += __shfl_xor_sync(0xffffffffu, v, 1);
        v += __shfl_xor_sync(0xffffffffu, v, 2);
        if (kq == 0) ps[r][c2] = v;
    }
    __syncthreads();

    for (int i = tid; i < RB * 128; i += 512) {
        int r = i >> 7, cc = i & 127;
        int gc = colg * 128 + cc; int d2 = gc >= 384; int rw = gc - d2 * 384;
        g_xg[(size_t)d2 * M_M * 384 + (size_t)(m0 + r) * 384 + rw] = ps[r][cc] + (d2 ? biB : biF)[rw];
    }
}

// ---------------- K2/K5: persistent BiGRU recurrence, 2-way k-split (768 thr) ----------------
// thread = (g = tid%384 weight row, kh = tid/384 K-half). Partials via shared.
template <int NB>
__global__ __launch_bounds__(768, 1)
void gru_kernel(const float* __restrict__ WhF, const float* __restrict__ WhB,
                const float* __restrict__ bhF, const float* __restrict__ bhB,
                const int* __restrict__ lens, int nSeq, int T)
{
    extern __shared__ __align__(16) float sh[];
    float* hs   = sh;                         // [NB*128]
    float* HG   = hs + NB * 128;              // [384*(NB+1)]
    float* XN   = HG + 384 * (NB + 1);        // [128*(NB+1)]
    float* ps   = XN + 128 * (NB + 1);        // [NB*768]
    float* sbias= ps + NB * 768;              // [384]
    __shared__ int slen[NB];

    const int dir  = blockIdx.x;
    const int seq0 = blockIdx.y * NB;
    const int tid  = threadIdx.x;
    const int g    = tid % 384;
    const int kh   = tid / 384;               // warp-uniform (384 = 12 warps)

    const float* W = dir ? WhB : WhF;
    ull w2[32];
    loadW<16>(w2, W + (size_t)g * 128 + kh * 64);

    for (int i = tid; i < NB * 128; i += 768) hs[i] = 0.f;
    if (tid < 384) sbias[tid] = (dir ? bhB : bhF)[tid];
    if (tid < NB) slen[tid] = lens ? lens[seq0 + tid] : T;
    const float* xgD = g_xg + (size_t)dir * nSeq * T * 384;
    __syncthreads();

    const int k   = tid & 127;   // phase-2 mapping
    const int sub = tid >> 7;    // 0..5

    for (int t = 0; t < T; t++) {
        // phase 1a: half-dot partials for all b
#pragma unroll 1
        for (int b = 0; b < NB; b++)
            ps[b * 768 + tid] = dotT<16>(w2, hs + b * 128 + kh * 64);
        __syncthreads();
        // phase 1b: combine halves + bias + xg
        for (int i = tid; i < NB * 384; i += 768) {
            int b = i / 384, gg = i % 384;
            float hgv = ps[b * 768 + gg] + ps[b * 768 + gg + 384] + sbias[gg];
            int lb = slen[b];
            int it = dir ? ((t < lb) ? (lb - 1 - t) : t) : t;
            float xv = xgD[((size_t)(seq0 + b) * T + it) * 384 + gg];
            if (gg < 256) HG[gg * (NB + 1) + b] = xv + hgv;
            else { HG[gg * (NB + 1) + b] = hgv; XN[(gg - 256) * (NB + 1) + b] = xv; }
        }
        __syncthreads();
        // phase 2: gates + state update + output (6-way b split)
#pragma unroll 1
        for (int b = sub; b < NB; b += 6) {
            int lb = slen[b];
            bool valid = t < lb;
            float r = sigmoidf_(HG[k * (NB + 1) + b]);
            float z = sigmoidf_(HG[(k + 128) * (NB + 1) + b]);
            float n = tanhf(XN[k * (NB + 1) + b] + r * HG[(k + 256) * (NB + 1) + b]);
            float h = hs[b * 128 + k];
            float hnew = valid ? ((1.f - z) * n + z * h) : h;
            hs[b * 128 + k] = hnew;
            int ot = dir ? (valid ? (lb - 1 - t) : t) : t;
            size_t m = (size_t)(seq0 + b) * T + ot;
            g_out[m * 256 + (size_t)dir * 128 + k] = valid ? hnew : 0.f;
        }
        __syncthreads();
    }
}

// ---------------- K3/K6: attention pooling (fused proj->logit->softmax->pool) ----------------
// 512 thr: thread = (c = tid>>2, kq = tid&3). Quarter-dot + 2 shfl (kq), tanh*ctx,
// then 3 shfl (c within warp) -> per-warp partial logits -> shared reduce -> softmax -> pool.
template <int T>
__global__ __launch_bounds__(512, 1)
void attn_kernel(const float* __restrict__ Wp, const float* __restrict__ bp,
                 const float* __restrict__ ctx)
{
    extern __shared__ __align__(16) float sh[];
    float* os    = sh;                 // [T*256]
    float* wpart = os + T * 256;       // [T*16]
    float* av    = wpart + T * 16;     // [T]
    __shared__ float mv, sv;

    const int word = blockIdx.x, tid = threadIdx.x;
    const int kq = tid & 3, c = tid >> 2;
    const int lane = tid & 31, warp = tid >> 5;

    const float4* src4 = (const float4*)(g_out + (size_t)word * T * 256);
    float4* os4 = (float4*)os;
    for (int i = tid; i < T * 64; i += 512) os4[i] = src4[i];

    ull w2[32];
    loadW<16>(w2, Wp + (size_t)c * 256 + kq * 64);
    const float bb = bp[c], cw = ctx[c];
    __syncthreads();

#pragma unroll 1
    for (int t = 0; t < T; t++) {
        float v = dotT<16>(w2, os + t * 256 + kq * 64);
        v += __shfl_xor_sync(0xffffffffu, v, 1);
        v += __shfl_xor_sync(0xffffffffu, v, 2);
        float tt = (kq == 0) ? tanhf(v + bb) * cw : 0.f;
        tt += __shfl_xor_sync(0xffffffffu, tt, 4);
        tt += __shfl_xor_sync(0xffffffffu, tt, 8);
        tt += __shfl_xor_sync(0xffffffffu, tt, 16);
        if (lane == 0) wpart[t * 16 + warp] = tt;
    }
    __syncthreads();
    if (tid < T) {
        float s = 0.f;
#pragma unroll
        for (int w = 0; w < 16; w++) s += wpart[tid * 16 + w];
        av[tid] = s;
    }
    __syncthreads();
    if (tid == 0) { float m = -1e30f; for (int t = 0; t < T; t++) m = fmaxf(m, av[t]); mv = m; }
    __syncthreads();
    if (tid < T) av[tid] = expf(av[tid] - mv);
    __syncthreads();
    if (tid == 0) { float s = 0.f; for (int t = 0; t < T; t++) s += av[t]; sv = 1.f / s; }
    __syncthreads();
    if (tid < 256) {
        float acc = 0.f;
#pragma unroll 4
        for (int t = 0; t < T; t++) acc += av[t] * os[t * 256 + tid];
        g_words[(size_t)word * 256 + tid] = acc * sv;
    }
}

// ---------------- K7: output head + writeback ----------------
__global__ __launch_bounds__(256, 1)
void final_kernel(const float* __restrict__ Wout, const float* __restrict__ bout,
                  float* __restrict__ out, int out_size)
{
    const int b = blockIdx.x, tid = threadIdx.x;
    const float* msg = g_words + (size_t)b * 256;
    const bool writeOut = (out_size != 32768);
    const bool writeMsg = (out_size >= 32768);
    const int msgOff = (out_size > 32768) ? 1024 : 0;
    if (writeMsg) out[msgOff + b * 256 + tid] = msg[tid];
    if (writeOut && tid < 8) {
        float acc = bout[tid];
        const float* wr = Wout + tid * 256;
        for (int kk = 0; kk < 256; kk++) acc += msg[kk] * wr[kk];
        out[b * 8 + tid] = acc;
    }
}

extern "C" void kernel_launch(void* const* d_in, const int* in_sizes, int n_in,
                              void* d_out, int out_size)
{
    const int*   chars  = (const int*)d_in[0];
    const int*   lens   = (const int*)d_in[1];
    const float* emb    = (const float*)d_in[2];
    const float* cWih_f = (const float*)d_in[3];
    const float* cWhh_f = (const float*)d_in[4];
    const float* cbih_f = (const float*)d_in[5];
    const float* cbhh_f = (const float*)d_in[6];
    const float* cWih_b = (const float*)d_in[7];
    const float* cWhh_b = (const float*)d_in[8];
    const float* cbih_b = (const float*)d_in[9];
    const float* cbhh_b = (const float*)d_in[10];
    const float* mWih_f = (const float*)d_in[11];
    const float* mWhh_f = (const float*)d_in[12];
    const float* mbih_f = (const float*)d_in[13];
    const float* mbhh_f = (const float*)d_in[14];
    const float* mWih_b = (const float*)d_in[15];
    const float* mWhh_b = (const float*)d_in[16];
    const float* mbih_b = (const float*)d_in[17];
    const float* mbhh_b = (const float*)d_in[18];
    const float* wWp    = (const float*)d_in[19];
    const float* wbp    = (const float*)d_in[20];
    const float* wctx   = (const float*)d_in[21];
    const float* pWp    = (const float*)d_in[22];
    const float* pbp    = (const float*)d_in[23];
    const float* pctx   = (const float*)d_in[24];
    const float* Wout   = (const float*)d_in[25];
    const float* bout   = (const float*)d_in[26];

    // dynamic shared sizes
    const int smG16 = (16 * 128 + 384 * 17 + 128 * 17 + 16 * 768 + 384) * 4;   // 93696 B
    const int smG4  = (4 * 128 + 384 * 5 + 128 * 5 + 4 * 768 + 384) * 4;       // 26112 B
    const int smA48 = (48 * 256 + 48 * 16 + 48) * 4;                           // 52416 B
    const int smA64 = (64 * 256 + 64 * 16 + 64) * 4;                           // 69888 B
    cudaFuncSetAttribute(gru_kernel<16>, cudaFuncAttributeMaxDynamicSharedMemorySize, smG16);
    cudaFuncSetAttribute(gru_kernel<4>,  cudaFuncAttributeMaxDynamicSharedMemorySize, smG4);
    cudaFuncSetAttribute(attn_kernel<48>, cudaFuncAttributeMaxDynamicSharedMemorySize, smA48);
    cudaFuncSetAttribute(attn_kernel<64>, cudaFuncAttributeMaxDynamicSharedMemorySize, smA64);

    // char level
    xg_char_kernel<<<dim3(3, 4096), 256>>>(chars, emb, cWih_f, cWih_b, cbih_f, cbih_b);
    gru_kernel<16><<<dim3(2, 512), 768, smG16>>>(cWhh_f, cWhh_b, cbhh_f, cbhh_b, lens, NSEQ_C, T_CH);
    attn_kernel<48><<<NSEQ_C, 512, smA48>>>(wWp, wbp, wctx);
    // message level
    xg_k256_kernel<<<dim3(6, 512), 512>>>(mWih_f, mWih_b, mbih_f, mbih_b);
    gru_kernel<4><<<dim3(2, 32), 768, smG4>>>(mWhh_f, mWhh_b, mbhh_f, mbhh_b, nullptr, 128, 64);
    attn_kernel<64><<<128, 512, smA64>>>(pWp, pbp, pctx);
    // head + writeback
    final_kernel<<<128, 256>>>(Wout, bout, (float*)d_out, out_size);
}

// round 12
// speedup vs baseline: 1.4690x; 1.4690x over previous
#include <cuda_runtime.h>
#include <math.h>

typedef unsigned long long ull;

// Shapes
#define NSEQ_C 8192            // B*W
#define T_CH   48              // chars per word
#define M_C    (NSEQ_C*T_CH)   // 393216 char rows
#define M_M    8192            // msg-level rows (B*W)

// ---------------- static device scratch (no allocations allowed) ----------------
__device__ float g_xg[301989888ull];        // [2][M][384] gate preacts
__device__ float g_out[100663296ull];       // [M][256] BiGRU outputs
__device__ float g_words[2097152ull];       // [8192][256] pooled word vectors / messages

// ---------------- helpers ----------------
__device__ __forceinline__ void ffma2(ull &d, ull a, ull b) {
    asm("fma.rn.f32x2 %0, %1, %2, %0;" : "+l"(d) : "l"(a), "l"(b));
}
__device__ __forceinline__ float f2sum(ull v) {
    unsigned lo, hi;
    asm("mov.b64 {%0,%1}, %2;" : "=r"(lo), "=r"(hi) : "l"(v));
    return __uint_as_float(lo) + __uint_as_float(hi);
}
__device__ __forceinline__ float sigmoidf_(float x) { return 1.0f / (1.0f + expf(-x)); }

// Load NU*4 floats of a weight row into packed-f32x2 registers (16B loads).
template <int NU>
__device__ __forceinline__ void loadW(ull* w2, const float* __restrict__ W) {
    const ulonglong2* wr = (const ulonglong2*)W;
#pragma unroll
    for (int j = 0; j < NU; j++) { ulonglong2 v = wr[j]; w2[2 * j] = v.x; w2[2 * j + 1] = v.y; }
}

// C simultaneous dot products over NU*4 floats of x (one broadcast LDS.128 feeds 2*C FFMA2).
// w layout: w[c*2*NU + idx].
template <int C, int NU>
__device__ __forceinline__ void dotC(const ull* w, const float* xp, float* o) {
    const ulonglong2* xr = (const ulonglong2*)xp;
    ull a[C];
#pragma unroll
    for (int c = 0; c < C; c++) a[c] = 0;
#pragma unroll
    for (int j = 0; j < NU; j++) {
        ulonglong2 v = xr[j];
#pragma unroll
        for (int c = 0; c < C; c++) {
            ffma2(a[c], w[c * 2 * NU + 2 * j],     v.x);
            ffma2(a[c], w[c * 2 * NU + 2 * j + 1], v.y);
        }
    }
#pragma unroll
    for (int c = 0; c < C; c++) o[c] = f2sum(a[c]);
}

// ---------------- K1: char input gates, fused embedding gather (K=64) ----------------
// Block: 256 thr, cols = 256 per block (C=4), kq = tid>>6 (4-way K split, warp-uniform).
__global__ __launch_bounds__(256, 2)
void xg_char_kernel(const int* __restrict__ chars, const float* __restrict__ emb,
                    const float* __restrict__ WihF, const float* __restrict__ WihB,
                    const float* __restrict__ biF,  const float* __restrict__ biB)
{
    const int RB = 96, RCH = 16;
    extern __shared__ __align__(16) float sh[];
    float* xs = sh;                 // [96][64]
    float* ps = xs + RB * 64;       // [16][4*256]
    float* sb = ps + RCH * 1024;    // [256]

    const int colg = blockIdx.x;    // 0..2 (256 cols each)
    const int m0   = blockIdx.y * RB;
    const int tid  = threadIdx.x;
    const int kq = tid >> 6, cl = tid & 63;

    ull w[4 * 8];                   // 4 cols x NU=4 -> 8 ull each
#pragma unroll
    for (int ci = 0; ci < 4; ci++) {
        int gcol = colg * 256 + cl + 64 * ci;
        int d = gcol >= 384, rw = gcol - d * 384;
        loadW<4>(w + ci * 8, (d ? WihB : WihF) + (size_t)rw * 64 + kq * 16);
    }
    {
        int gcol = colg * 256 + tid;
        int d = gcol >= 384, rw = gcol - d * 384;
        sb[tid] = (d ? biB : biF)[rw];
    }

    float4* xs4 = (float4*)xs;
    const float4* emb4 = (const float4*)emb;
    for (int idx = tid; idx < RB * 16; idx += 256) {
        int r = idx >> 4, q = idx & 15;
        int ch = chars[m0 + r];
        xs4[idx] = emb4[(size_t)ch * 16 + q];
    }
    __syncthreads();

    for (int ch = 0; ch < RB / RCH; ch++) {
        int r0 = ch * RCH;
#pragma unroll 2
        for (int rl = 0; rl < RCH; rl++) {
            float o[4];
            dotC<4, 4>(w, xs + (r0 + rl) * 64 + kq * 16, o);
#pragma unroll
            for (int ci = 0; ci < 4; ci++)
                ps[rl * 1024 + kq * 256 + cl + 64 * ci] = o[ci];
        }
        __syncthreads();
        for (int p = 0; p < 16; p++) {
            int i = tid + p * 256;
            int rl = i >> 8, col = i & 255;
            float v = ps[rl * 1024 + col] + ps[rl * 1024 + 256 + col]
                    + ps[rl * 1024 + 512 + col] + ps[rl * 1024 + 768 + col] + sb[col];
            int gcol = colg * 256 + col;
            int d = gcol >= 384, rw = gcol - d * 384;
            g_xg[(size_t)d * M_C * 384 + (size_t)(m0 + r0 + rl) * 384 + rw] = v;
        }
        __syncthreads();
    }
}

// ---------------- K4: message input gates GEMM (K=256) ----------------
// Block covers 128 cols (C=4), kq = tid>>5 (8-way, warp-uniform).
__global__ __launch_bounds__(256, 1)
void xg_k256_kernel(const float* __restrict__ WihF, const float* __restrict__ WihB,
                    const float* __restrict__ biF,  const float* __restrict__ biB)
{
    const int RB = 16;
    extern __shared__ __align__(16) float sh[];
    float* xs = sh;                 // [16][256]
    float* ps = xs + RB * 256;      // [16][8*128]
    float* sb = ps + RB * 1024;     // [128]

    const int colg = blockIdx.x;    // 0..5
    const int m0   = blockIdx.y * RB;
    const int tid  = threadIdx.x;
    const int kq = tid >> 5, cl = tid & 31;

    ull w[4 * 16];                  // 4 cols x NU=8 -> 16 ull each
#pragma unroll
    for (int ci = 0; ci < 4; ci++) {
        int gcol = colg * 128 + cl + 32 * ci;
        int d = gcol >= 384, rw = gcol - d * 384;
        loadW<8>(w + ci * 16, (d ? WihB : WihF) + (size_t)rw * 256 + kq * 32);
    }
    if (tid < 128) {
        int gcol = colg * 128 + tid;
        int d = gcol >= 384, rw = gcol - d * 384;
        sb[tid] = (d ? biB : biF)[rw];
    }

    float4* xs4 = (float4*)xs;
    const float4* X4 = (const float4*)(g_words + (size_t)m0 * 256);
    for (int i = tid; i < RB * 64; i += 256) xs4[i] = X4[i];
    __syncthreads();

#pragma unroll 2
    for (int r = 0; r < RB; r++) {
        float o[4];
        dotC<4, 8>(w, xs + r * 256 + kq * 32, o);
#pragma unroll
        for (int ci = 0; ci < 4; ci++)
            ps[r * 1024 + kq * 128 + cl + 32 * ci] = o[ci];
    }
    __syncthreads();

    for (int p = 0; p < 8; p++) {
        int i = tid + p * 256;
        int r = i >> 7, col = i & 127;
        float v = sb[col];
#pragma unroll
        for (int q = 0; q < 8; q++) v += ps[r * 1024 + q * 128 + col];
        int gcol = colg * 128 + col;
        int d = gcol >= 384, rw = gcol - d * 384;
        g_xg[(size_t)d * M_M * 384 + (size_t)(m0 + r) * 384 + rw] = v;
    }
}

// ---------------- K2/K5: persistent BiGRU recurrence ----------------
// 256 thr: cl = tid&63 (cols cl+64*ci, ci<6), kq = tid>>6 (4-way K split, warp-uniform).
// Whh in 192 regs/thread. Partials -> shared ps (coalesced), combine adds bias+xg.
template <int NB, int BC>
__global__ __launch_bounds__(256, 1)
void gru_kernel(const float* __restrict__ WhF, const float* __restrict__ WhB,
                const float* __restrict__ bhF, const float* __restrict__ bhB,
                const int* __restrict__ lens, int nSeq, int T)
{
    extern __shared__ __align__(16) float sh[];
    float* hs    = sh;                          // [NB*128]
    float* HG    = hs + NB * 128;               // [384*(NB+1)]
    float* XN    = HG + 384 * (NB + 1);         // [128*(NB+1)]
    float* ps    = XN + 128 * (NB + 1);         // [BC*1536]
    float* sbias = ps + BC * 1536;              // [384]
    __shared__ int slen[NB];

    const int dir  = blockIdx.x;
    const int seq0 = blockIdx.y * NB;
    const int tid  = threadIdx.x;
    const int kq = tid >> 6, cl = tid & 63;

    const float* W = dir ? WhB : WhF;
    ull w[6 * 16];                               // 6 cols x NU=8
#pragma unroll
    for (int ci = 0; ci < 6; ci++)
        loadW<8>(w + ci * 16, W + (size_t)(cl + 64 * ci) * 128 + kq * 32);

    for (int i = tid; i < NB * 128; i += 256) hs[i] = 0.f;
    for (int i = tid; i < 384; i += 256) sbias[i] = (dir ? bhB : bhF)[i];
    if (tid < NB) slen[tid] = lens ? lens[seq0 + tid] : T;
    const float* xgD = g_xg + (size_t)dir * nSeq * T * 384;
    __syncthreads();

    const int k   = tid & 127;
    const int sub = tid >> 7;        // 0..1

    for (int t = 0; t < T; t++) {
        for (int bc = 0; bc < NB / BC; bc++) {
            // phase 1a: partial dots for BC sequences
#pragma unroll 1
            for (int bl = 0; bl < BC; bl++) {
                int b = bc * BC + bl;
                float o[6];
                dotC<6, 8>(w, hs + b * 128 + kq * 32, o);
#pragma unroll
                for (int ci = 0; ci < 6; ci++)
                    ps[bl * 1536 + kq * 384 + cl + 64 * ci] = o[ci];
            }
            __syncthreads();
            // phase 1b: combine kq parts + bias + xg -> HG/XN
            for (int i = tid; i < BC * 384; i += 256) {
                int bl = i / 384, gg = i - bl * 384;
                int b = bc * BC + bl;
                float v = ps[bl * 1536 + gg] + ps[bl * 1536 + 384 + gg]
                        + ps[bl * 1536 + 768 + gg] + ps[bl * 1536 + 1152 + gg] + sbias[gg];
                int lb = slen[b];
                int it = dir ? ((t < lb) ? (lb - 1 - t) : t) : t;
                float xv = xgD[((size_t)(seq0 + b) * T + it) * 384 + gg];
                if (gg < 256) HG[gg * (NB + 1) + b] = xv + v;
                else { HG[gg * (NB + 1) + b] = v; XN[(gg - 256) * (NB + 1) + b] = xv; }
            }
            __syncthreads();
        }
        // phase 2: gates + state update + output
#pragma unroll 1
        for (int b = sub; b < NB; b += 2) {
            int lb = slen[b];
            bool valid = t < lb;
            float r = sigmoidf_(HG[k * (NB + 1) + b]);
            float z = sigmoidf_(HG[(k + 128) * (NB + 1) + b]);
            float n = tanhf(XN[k * (NB + 1) + b] + r * HG[(k + 256) * (NB + 1) + b]);
            float h = hs[b * 128 + k];
            float hnew = valid ? ((1.f - z) * n + z * h) : h;
            hs[b * 128 + k] = hnew;
            int ot = dir ? (valid ? (lb - 1 - t) : t) : t;
            size_t m = (size_t)(seq0 + b) * T + ot;
            g_out[m * 256 + (size_t)dir * 128 + k] = valid ? hnew : 0.f;
        }
        __syncthreads();
    }
}

// ---------------- K3/K6: attention pooling ----------------
// 256 thr: cl = tid&31 (cols cl+32*ci, ci<4), kq = tid>>5 (8-way K split, warp-uniform).
// Processes 4 t per chunk: partial dots -> ps, combine: sum kq, tanh*ctx, warp-reduce -> wpart.
template <int T>
__global__ __launch_bounds__(256, 1)
void attn_kernel(const float* __restrict__ Wp, const float* __restrict__ bp,
                 const float* __restrict__ ctx)
{
    extern __shared__ __align__(16) float sh[];
    float* os    = sh;                 // [T*256]
    float* ps    = os + T * 256;       // [4][8*128]
    float* wpart = ps + 4096;          // [T*4]
    float* av    = wpart + T * 4;      // [T]
    float* sbp   = av + T;             // [128]
    float* sctx  = sbp + 128;          // [128]
    __shared__ float mv, sv;

    const int word = blockIdx.x, tid = threadIdx.x;
    const int kq = tid >> 5, cl = tid & 31;

    const float4* src4 = (const float4*)(g_out + (size_t)word * T * 256);
    float4* os4 = (float4*)os;
    for (int i = tid; i < T * 64; i += 256) os4[i] = src4[i];
    if (tid < 128) { sbp[tid] = bp[tid]; sctx[tid] = ctx[tid]; }

    ull w[4 * 16];                     // 4 cols x NU=8
#pragma unroll
    for (int ci = 0; ci < 4; ci++)
        loadW<8>(w + ci * 16, Wp + (size_t)(cl + 32 * ci) * 256 + kq * 32);
    __syncthreads();

    for (int it = 0; it < T / 4; it++) {
#pragma unroll
        for (int tt = 0; tt < 4; tt++) {
            int t = it * 4 + tt;
            float o[4];
            dotC<4, 8>(w, os + t * 256 + kq * 32, o);
#pragma unroll
            for (int ci = 0; ci < 4; ci++)
                ps[tt * 1024 + kq * 128 + cl + 32 * ci] = o[ci];
        }
        __syncthreads();
#pragma unroll
        for (int p = 0; p < 2; p++) {
            int i = tid + p * 256;
            int tl = i >> 7, col = i & 127;
            float v = 0.f;
#pragma unroll
            for (int q = 0; q < 8; q++) v += ps[tl * 1024 + q * 128 + col];
            float tv = tanhf(v + sbp[col]) * sctx[col];
#pragma unroll
            for (int off = 16; off > 0; off >>= 1) tv += __shfl_xor_sync(0xffffffffu, tv, off);
            if ((tid & 31) == 0) wpart[(it * 4 + tl) * 4 + ((col >> 5) & 3)] = tv;
        }
        __syncthreads();
    }

    if (tid < T) av[tid] = wpart[tid * 4] + wpart[tid * 4 + 1] + wpart[tid * 4 + 2] + wpart[tid * 4 + 3];
    __syncthreads();
    if (tid == 0) { float m = -1e30f; for (int t = 0; t < T; t++) m = fmaxf(m, av[t]); mv = m; }
    __syncthreads();
    if (tid < T) av[tid] = expf(av[tid] - mv);
    __syncthreads();
    if (tid == 0) { float s = 0.f; for (int t = 0; t < T; t++) s += av[t]; sv = 1.f / s; }
    __syncthreads();
    float acc = 0.f;
#pragma unroll 4
    for (int t = 0; t < T; t++) acc += av[t] * os[t * 256 + tid];
    g_words[(size_t)word * 256 + tid] = acc * sv;
}

// ---------------- K7: output head + writeback ----------------
__global__ __launch_bounds__(256, 1)
void final_kernel(const float* __restrict__ Wout, const float* __restrict__ bout,
                  float* __restrict__ out, int out_size)
{
    const int b = blockIdx.x, tid = threadIdx.x;
    const float* msg = g_words + (size_t)b * 256;
    const bool writeOut = (out_size != 32768);
    const bool writeMsg = (out_size >= 32768);
    const int msgOff = (out_size > 32768) ? 1024 : 0;
    if (writeMsg) out[msgOff + b * 256 + tid] = msg[tid];
    if (writeOut && tid < 8) {
        float acc = bout[tid];
        const float* wr = Wout + tid * 256;
        for (int kk = 0; kk < 256; kk++) acc += msg[kk] * wr[kk];
        out[b * 8 + tid] = acc;
    }
}

extern "C" void kernel_launch(void* const* d_in, const int* in_sizes, int n_in,
                              void* d_out, int out_size)
{
    const int*   chars  = (const int*)d_in[0];
    const int*   lens   = (const int*)d_in[1];
    const float* emb    = (const float*)d_in[2];
    const float* cWih_f = (const float*)d_in[3];
    const float* cWhh_f = (const float*)d_in[4];
    const float* cbih_f = (const float*)d_in[5];
    const float* cbhh_f = (const float*)d_in[6];
    const float* cWih_b = (const float*)d_in[7];
    const float* cWhh_b = (const float*)d_in[8];
    const float* cbih_b = (const float*)d_in[9];
    const float* cbhh_b = (const float*)d_in[10];
    const float* mWih_f = (const float*)d_in[11];
    const float* mWhh_f = (const float*)d_in[12];
    const float* mbih_f = (const float*)d_in[13];
    const float* mbhh_f = (const float*)d_in[14];
    const float* mWih_b = (const float*)d_in[15];
    const float* mWhh_b = (const float*)d_in[16];
    const float* mbih_b = (const float*)d_in[17];
    const float* mbhh_b = (const float*)d_in[18];
    const float* wWp    = (const float*)d_in[19];
    const float* wbp    = (const float*)d_in[20];
    const float* wctx   = (const float*)d_in[21];
    const float* pWp    = (const float*)d_in[22];
    const float* pbp    = (const float*)d_in[23];
    const float* pctx   = (const float*)d_in[24];
    const float* Wout   = (const float*)d_in[25];
    const float* bout   = (const float*)d_in[26];

    const int smXC  = (96 * 64 + 16 * 1024 + 256) * 4;                               // 91136
    const int smK   = (16 * 256 + 16 * 1024 + 128) * 4;                              // 82432
    const int smG16 = (16 * 128 + 384 * 17 + 128 * 17 + 8 * 1536 + 384) * 4;         // 93696
    const int smG4  = (4 * 128 + 384 * 5 + 128 * 5 + 4 * 1536 + 384) * 4;            // 38400
    const int smA48 = (48 * 256 + 4096 + 48 * 4 + 48 + 256) * 4;                     // 67520
    const int smA64 = (64 * 256 + 4096 + 64 * 4 + 64 + 256) * 4;                     // 84224

    cudaFuncSetAttribute(xg_char_kernel,   cudaFuncAttributeMaxDynamicSharedMemorySize, smXC);
    cudaFuncSetAttribute(xg_k256_kernel,   cudaFuncAttributeMaxDynamicSharedMemorySize, smK);
    cudaFuncSetAttribute(gru_kernel<16,8>, cudaFuncAttributeMaxDynamicSharedMemorySize, smG16);
    cudaFuncSetAttribute(gru_kernel<4,4>,  cudaFuncAttributeMaxDynamicSharedMemorySize, smG4);
    cudaFuncSetAttribute(attn_kernel<48>,  cudaFuncAttributeMaxDynamicSharedMemorySize, smA48);
    cudaFuncSetAttribute(attn_kernel<64>,  cudaFuncAttributeMaxDynamicSharedMemorySize, smA64);

    // char level
    xg_char_kernel<<<dim3(3, 4096), 256, smXC>>>(chars, emb, cWih_f, cWih_b, cbih_f, cbih_b);
    gru_kernel<16,8><<<dim3(2, 512), 256, smG16>>>(cWhh_f, cWhh_b, cbhh_f, cbhh_b, lens, NSEQ_C, T_CH);
    attn_kernel<48><<<NSEQ_C, 256, smA48>>>(wWp, wbp, wctx);
    // message level
    xg_k256_kernel<<<dim3(6, 512), 256, smK>>>(mWih_f, mWih_b, mbih_f, mbih_b);
    gru_kernel<4,4><<<dim3(2, 32), 256, smG4>>>(mWhh_f, mWhh_b, mbhh_f, mbhh_b, nullptr, 128, 64);
    attn_kernel<64><<<128, 256, smA64>>>(pWp, pbp, pctx);
    // head + writeback
    final_kernel<<<128, 256>>>(Wout, bout, (float*)d_out, out_size);
}

// round 13
// speedup vs baseline: 1.7859x; 1.2157x over previous
#include <cuda_runtime.h>
#include <math.h>

typedef unsigned long long ull;

// Shapes
#define NSEQ_C 8192            // B*W
#define T_CH   48              // chars per word
#define M_C    (NSEQ_C*T_CH)   // 393216 char rows
#define M_M    8192            // msg-level rows (B*W)

// ---------------- static device scratch (no allocations allowed) ----------------
__device__ float g_xg[301989888ull];        // [2][M][384] gate preacts
__device__ float g_out[100663296ull];       // [M][256] BiGRU outputs
__device__ float g_words[2097152ull];       // [8192][256] pooled word vectors / messages

// ---------------- helpers ----------------
__device__ __forceinline__ void ffma2(ull &d, ull a, ull b) {
    asm("fma.rn.f32x2 %0, %1, %2, %0;" : "+l"(d) : "l"(a), "l"(b));
}
__device__ __forceinline__ float f2sum(ull v) {
    unsigned lo, hi;
    asm("mov.b64 {%0,%1}, %2;" : "=r"(lo), "=r"(hi) : "l"(v));
    return __uint_as_float(lo) + __uint_as_float(hi);
}
__device__ __forceinline__ float sigmoidf_(float x) { return 1.0f / (1.0f + expf(-x)); }

// Load NU*4 floats of a weight row into packed-f32x2 registers (16B loads).
template <int NU>
__device__ __forceinline__ void loadW(ull* w2, const float* __restrict__ W) {
    const ulonglong2* wr = (const ulonglong2*)W;
#pragma unroll
    for (int j = 0; j < NU; j++) { ulonglong2 v = wr[j]; w2[2 * j] = v.x; w2[2 * j + 1] = v.y; }
}

// C simultaneous dot products over NU*4 floats of x. x address is warp-uniform
// (pure LDS broadcast), so one LDS.128 feeds 2*C FFMA2.
template <int C, int NU>
__device__ __forceinline__ void dotC(const ull* w, const float* xp, float* o) {
    const ulonglong2* xr = (const ulonglong2*)xp;
    ull a[C];
#pragma unroll
    for (int c = 0; c < C; c++) a[c] = 0;
#pragma unroll
    for (int j = 0; j < NU; j++) {
        ulonglong2 v = xr[j];
#pragma unroll
        for (int c = 0; c < C; c++) {
            ffma2(a[c], w[c * 2 * NU + 2 * j],     v.x);
            ffma2(a[c], w[c * 2 * NU + 2 * j + 1], v.y);
        }
    }
#pragma unroll
    for (int c = 0; c < C; c++) o[c] = f2sum(a[c]);
}

// ---------------- K1: char input gates, fused embedding gather (K=64) ----------------
// 256 thr, 256 cols/block (C=4), kq = tid>>6 (4-way K split, warp-uniform).
__global__ __launch_bounds__(256, 2)
void xg_char_kernel(const int* __restrict__ chars, const float* __restrict__ emb,
                    const float* __restrict__ WihF, const float* __restrict__ WihB,
                    const float* __restrict__ biF,  const float* __restrict__ biB)
{
    const int RB = 96, RCH = 16;
    extern __shared__ __align__(16) float sh[];
    float* xs = sh;                 // [96][64]
    float* ps = xs + RB * 64;       // [16][4*256]
    float* sb = ps + RCH * 1024;    // [256]

    const int colg = blockIdx.x;    // 0..2
    const int m0   = blockIdx.y * RB;
    const int tid  = threadIdx.x;
    const int kq = tid >> 6, cl = tid & 63;

    ull w[4 * 8];
#pragma unroll
    for (int ci = 0; ci < 4; ci++) {
        int gcol = colg * 256 + cl + 64 * ci;
        int d = gcol >= 384, rw = gcol - d * 384;
        loadW<4>(w + ci * 8, (d ? WihB : WihF) + (size_t)rw * 64 + kq * 16);
    }
    {
        int gcol = colg * 256 + tid;
        int d = gcol >= 384, rw = gcol - d * 384;
        sb[tid] = (d ? biB : biF)[rw];
    }

    float4* xs4 = (float4*)xs;
    const float4* emb4 = (const float4*)emb;
    for (int idx = tid; idx < RB * 16; idx += 256) {
        int r = idx >> 4, q = idx & 15;
        int ch = chars[m0 + r];
        xs4[idx] = emb4[(size_t)ch * 16 + q];
    }
    __syncthreads();

    for (int chk = 0; chk < RB / RCH; chk++) {
        int r0 = chk * RCH;
#pragma unroll 2
        for (int rl = 0; rl < RCH; rl++) {
            float o[4];
            dotC<4, 4>(w, xs + (r0 + rl) * 64 + kq * 16, o);
#pragma unroll
            for (int ci = 0; ci < 4; ci++)
                ps[rl * 1024 + kq * 256 + cl + 64 * ci] = o[ci];
        }
        __syncthreads();
        for (int p = 0; p < 16; p++) {
            int i = tid + p * 256;
            int rl = i >> 8, col = i & 255;
            float v = ps[rl * 1024 + col] + ps[rl * 1024 + 256 + col]
                    + ps[rl * 1024 + 512 + col] + ps[rl * 1024 + 768 + col] + sb[col];
            int gcol = colg * 256 + col;
            int d = gcol >= 384, rw = gcol - d * 384;
            g_xg[(size_t)d * M_C * 384 + (size_t)(m0 + r0 + rl) * 384 + rw] = v;
        }
        __syncthreads();
    }
}

// ---------------- K4: message input gates GEMM (K=256) ----------------
__global__ __launch_bounds__(256, 1)
void xg_k256_kernel(const float* __restrict__ WihF, const float* __restrict__ WihB,
                    const float* __restrict__ biF,  const float* __restrict__ biB)
{
    const int RB = 16;
    extern __shared__ __align__(16) float sh[];
    float* xs = sh;                 // [16][256]
    float* ps = xs + RB * 256;      // [16][8*128]
    float* sb = ps + RB * 1024;     // [128]

    const int colg = blockIdx.x;    // 0..5
    const int m0   = blockIdx.y * RB;
    const int tid  = threadIdx.x;
    const int kq = tid >> 5, cl = tid & 31;

    ull w[4 * 16];
#pragma unroll
    for (int ci = 0; ci < 4; ci++) {
        int gcol = colg * 128 + cl + 32 * ci;
        int d = gcol >= 384, rw = gcol - d * 384;
        loadW<8>(w + ci * 16, (d ? WihB : WihF) + (size_t)rw * 256 + kq * 32);
    }
    if (tid < 128) {
        int gcol = colg * 128 + tid;
        int d = gcol >= 384, rw = gcol - d * 384;
        sb[tid] = (d ? biB : biF)[rw];
    }

    float4* xs4 = (float4*)xs;
    const float4* X4 = (const float4*)(g_words + (size_t)m0 * 256);
    for (int i = tid; i < RB * 64; i += 256) xs4[i] = X4[i];
    __syncthreads();

#pragma unroll 2
    for (int r = 0; r < RB; r++) {
        float o[4];
        dotC<4, 8>(w, xs + r * 256 + kq * 32, o);
#pragma unroll
        for (int ci = 0; ci < 4; ci++)
            ps[r * 1024 + kq * 128 + cl + 32 * ci] = o[ci];
    }
    __syncthreads();

    for (int p = 0; p < 8; p++) {
        int i = tid + p * 256;
        int r = i >> 7, col = i & 127;
        float v = sb[col];
#pragma unroll
        for (int q = 0; q < 8; q++) v += ps[r * 1024 + q * 128 + col];
        int gcol = colg * 128 + col;
        int d = gcol >= 384, rw = gcol - d * 384;
        g_xg[(size_t)d * M_M * 384 + (size_t)(m0 + r) * 384 + rw] = v;
    }
}

// ---------------- K2/K5: persistent BiGRU recurrence ----------------
// 384 thr (12 warps): kq = warp&3 (4-way K split), cgrp = warp>>2 (0..2),
// cl = cgrp*32+lane (0..95), C=4 cols (cl + 96*ci) -> 128 weight regs/thread.
template <int NB, int BC>
__global__ __launch_bounds__(384, 1)
void gru_kernel(const float* __restrict__ WhF, const float* __restrict__ WhB,
                const float* __restrict__ bhF, const float* __restrict__ bhB,
                const int* __restrict__ lens, int nSeq, int T)
{
    extern __shared__ __align__(16) float sh[];
    float* hs    = sh;                          // [NB*128]
    float* HG    = hs + NB * 128;               // [384*(NB+1)]
    float* XN    = HG + 384 * (NB + 1);         // [128*(NB+1)]
    float* ps    = XN + 128 * (NB + 1);         // [BC*1536]
    float* sbias = ps + BC * 1536;              // [384]
    __shared__ int slen[NB];

    const int dir  = blockIdx.x;
    const int seq0 = blockIdx.y * NB;
    const int tid  = threadIdx.x;
    const int warp = tid >> 5, lane = tid & 31;
    const int kq   = warp & 3;                  // warp-uniform
    const int cl   = (warp >> 2) * 32 + lane;   // 0..95

    const float* W = dir ? WhB : WhF;
    ull w[4 * 16];                              // 4 cols x NU=8 -> 128 regs
#pragma unroll
    for (int ci = 0; ci < 4; ci++)
        loadW<8>(w + ci * 16, W + (size_t)(cl + 96 * ci) * 128 + kq * 32);

    for (int i = tid; i < NB * 128; i += 384) hs[i] = 0.f;
    if (tid < 384) sbias[tid] = (dir ? bhB : bhF)[tid];
    if (tid < NB) slen[tid] = lens ? lens[seq0 + tid] : T;
    const float* xgD = g_xg + (size_t)dir * nSeq * T * 384;
    __syncthreads();

    const int k   = tid & 127;
    const int sub = tid >> 7;    // 0..2

    for (int t = 0; t < T; t++) {
        for (int bc = 0; bc < NB / BC; bc++) {
            // phase 1a: partial dots (x-reads are broadcasts)
#pragma unroll 1
            for (int bl = 0; bl < BC; bl++) {
                int b = bc * BC + bl;
                float o[4];
                dotC<4, 8>(w, hs + b * 128 + kq * 32, o);
#pragma unroll
                for (int ci = 0; ci < 4; ci++)
                    ps[bl * 1536 + kq * 384 + cl + 96 * ci] = o[ci];
            }
            __syncthreads();
            // phase 1b: combine kq parts + bias + xg
            for (int i = tid; i < BC * 384; i += 384) {
                int bl = i / 384, gg = i - bl * 384;
                int b = bc * BC + bl;
                float v = ps[bl * 1536 + gg] + ps[bl * 1536 + 384 + gg]
                        + ps[bl * 1536 + 768 + gg] + ps[bl * 1536 + 1152 + gg] + sbias[gg];
                int lb = slen[b];
                int it = dir ? ((t < lb) ? (lb - 1 - t) : t) : t;
                float xv = xgD[((size_t)(seq0 + b) * T + it) * 384 + gg];
                if (gg < 256) HG[gg * (NB + 1) + b] = xv + v;
                else { HG[gg * (NB + 1) + b] = v; XN[(gg - 256) * (NB + 1) + b] = xv; }
            }
            __syncthreads();
        }
        // phase 2: gates + state update + output
#pragma unroll 1
        for (int b = sub; b < NB; b += 3) {
            int lb = slen[b];
            bool valid = t < lb;
            float r = sigmoidf_(HG[k * (NB + 1) + b]);
            float z = sigmoidf_(HG[(k + 128) * (NB + 1) + b]);
            float n = tanhf(XN[k * (NB + 1) + b] + r * HG[(k + 256) * (NB + 1) + b]);
            float h = hs[b * 128 + k];
            float hnew = valid ? ((1.f - z) * n + z * h) : h;
            hs[b * 128 + k] = hnew;
            int ot = dir ? (valid ? (lb - 1 - t) : t) : t;
            size_t m = (size_t)(seq0 + b) * T + ot;
            g_out[m * 256 + (size_t)dir * 128 + k] = valid ? hnew : 0.f;
        }
        __syncthreads();
    }
}

// ---------------- K3/K6: attention pooling ----------------
// 512 thr (16 warps): kq = warp&7 (8-way K), cgrp = warp>>3 (0..1),
// cl = cgrp*32+lane (0..63), C=2 cols (cl + 64*ci) -> 64 weight regs.
template <int T>
__global__ __launch_bounds__(512, 1)
void attn_kernel(const float* __restrict__ Wp, const float* __restrict__ bp,
                 const float* __restrict__ ctx)
{
    const int CH = 8;
    extern __shared__ __align__(16) float sh[];
    float* os    = sh;                 // [T*256]
    float* ps    = os + T * 256;       // [CH][8*128]
    float* wpart = ps + CH * 1024;     // [T*4]
    float* av    = wpart + T * 4;      // [T]
    float* sbp   = av + T;             // [128]
    float* sctx  = sbp + 128;          // [128]
    __shared__ float mv, sv;

    const int word = blockIdx.x, tid = threadIdx.x;
    const int warp = tid >> 5, lane = tid & 31;
    const int kq   = warp & 7;                  // warp-uniform
    const int cl   = (warp >> 3) * 32 + lane;   // 0..63

    const float4* src4 = (const float4*)(g_out + (size_t)word * T * 256);
    float4* os4 = (float4*)os;
    for (int i = tid; i < T * 64; i += 512) os4[i] = src4[i];
    if (tid < 128) { sbp[tid] = bp[tid]; sctx[tid] = ctx[tid]; }

    ull w[2 * 16];                     // 2 cols x NU=8 -> 64 regs
#pragma unroll
    for (int ci = 0; ci < 2; ci++)
        loadW<8>(w + ci * 16, Wp + (size_t)(cl + 64 * ci) * 256 + kq * 32);
    __syncthreads();

    for (int it = 0; it < T / CH; it++) {
#pragma unroll
        for (int tt = 0; tt < CH; tt++) {
            int t = it * CH + tt;
            float o[2];
            dotC<2, 8>(w, os + t * 256 + kq * 32, o);
            ps[tt * 1024 + kq * 128 + cl]      = o[0];
            ps[tt * 1024 + kq * 128 + cl + 64] = o[1];
        }
        __syncthreads();
#pragma unroll
        for (int p = 0; p < 2; p++) {
            int i = tid + p * 512;
            int tl = i >> 7, col = i & 127;
            float v = 0.f;
#pragma unroll
            for (int q = 0; q < 8; q++) v += ps[tl * 1024 + q * 128 + col];
            float tv = tanhf(v + sbp[col]) * sctx[col];
#pragma unroll
            for (int off = 16; off > 0; off >>= 1) tv += __shfl_xor_sync(0xffffffffu, tv, off);
            if (lane == 0) wpart[(it * CH + tl) * 4 + ((col >> 5) & 3)] = tv;
        }
        __syncthreads();
    }

    if (tid < T) av[tid] = wpart[tid * 4] + wpart[tid * 4 + 1] + wpart[tid * 4 + 2] + wpart[tid * 4 + 3];
    __syncthreads();
    if (tid == 0) { float m = -1e30f; for (int t = 0; t < T; t++) m = fmaxf(m, av[t]); mv = m; }
    __syncthreads();
    if (tid < T) av[tid] = expf(av[tid] - mv);
    __syncthreads();
    if (tid == 0) { float s = 0.f; for (int t = 0; t < T; t++) s += av[t]; sv = 1.f / s; }
    __syncthreads();
    if (tid < 256) {
        float acc = 0.f;
#pragma unroll 4
        for (int t = 0; t < T; t++) acc += av[t] * os[t * 256 + tid];
        g_words[(size_t)word * 256 + tid] = acc * sv;
    }
}

// ---------------- K7: output head + writeback ----------------
__global__ __launch_bounds__(256, 1)
void final_kernel(const float* __restrict__ Wout, const float* __restrict__ bout,
                  float* __restrict__ out, int out_size)
{
    const int b = blockIdx.x, tid = threadIdx.x;
    const float* msg = g_words + (size_t)b * 256;
    const bool writeOut = (out_size != 32768);
    const bool writeMsg = (out_size >= 32768);
    const int msgOff = (out_size > 32768) ? 1024 : 0;
    if (writeMsg) out[msgOff + b * 256 + tid] = msg[tid];
    if (writeOut && tid < 8) {
        float acc = bout[tid];
        const float* wr = Wout + tid * 256;
        for (int kk = 0; kk < 256; kk++) acc += msg[kk] * wr[kk];
        out[b * 8 + tid] = acc;
    }
}

extern "C" void kernel_launch(void* const* d_in, const int* in_sizes, int n_in,
                              void* d_out, int out_size)
{
    const int*   chars  = (const int*)d_in[0];
    const int*   lens   = (const int*)d_in[1];
    const float* emb    = (const float*)d_in[2];
    const float* cWih_f = (const float*)d_in[3];
    const float* cWhh_f = (const float*)d_in[4];
    const float* cbih_f = (const float*)d_in[5];
    const float* cbhh_f = (const float*)d_in[6];
    const float* cWih_b = (const float*)d_in[7];
    const float* cWhh_b = (const float*)d_in[8];
    const float* cbih_b = (const float*)d_in[9];
    const float* cbhh_b = (const float*)d_in[10];
    const float* mWih_f = (const float*)d_in[11];
    const float* mWhh_f = (const float*)d_in[12];
    const float* mbih_f = (const float*)d_in[13];
    const float* mbhh_f = (const float*)d_in[14];
    const float* mWih_b = (const float*)d_in[15];
    const float* mWhh_b = (const float*)d_in[16];
    const float* mbih_b = (const float*)d_in[17];
    const float* mbhh_b = (const float*)d_in[18];
    const float* wWp    = (const float*)d_in[19];
    const float* wbp    = (const float*)d_in[20];
    const float* wctx   = (const float*)d_in[21];
    const float* pWp    = (const float*)d_in[22];
    const float* pbp    = (const float*)d_in[23];
    const float* pctx   = (const float*)d_in[24];
    const float* Wout   = (const float*)d_in[25];
    const float* bout   = (const float*)d_in[26];

    const int smXC  = (96 * 64 + 16 * 1024 + 256) * 4;                               // 91136
    const int smK   = (16 * 256 + 16 * 1024 + 128) * 4;                              // 82432
    const int smG16 = (16 * 128 + 384 * 17 + 128 * 17 + 8 * 1536 + 384) * 4;         // 93696
    const int smG4  = (4 * 128 + 384 * 5 + 128 * 5 + 4 * 1536 + 384) * 4;            // 38400
    const int smA48 = (48 * 256 + 8 * 1024 + 48 * 4 + 48 + 256) * 4;                 // 83904
    const int smA64 = (64 * 256 + 8 * 1024 + 64 * 4 + 64 + 256) * 4;                 // 100608

    cudaFuncSetAttribute(xg_char_kernel,   cudaFuncAttributeMaxDynamicSharedMemorySize, smXC);
    cudaFuncSetAttribute(xg_k256_kernel,   cudaFuncAttributeMaxDynamicSharedMemorySize, smK);
    cudaFuncSetAttribute(gru_kernel<16,8>, cudaFuncAttributeMaxDynamicSharedMemorySize, smG16);
    cudaFuncSetAttribute(gru_kernel<4,4>,  cudaFuncAttributeMaxDynamicSharedMemorySize, smG4);
    cudaFuncSetAttribute(attn_kernel<48>,  cudaFuncAttributeMaxDynamicSharedMemorySize, smA48);
    cudaFuncSetAttribute(attn_kernel<64>,  cudaFuncAttributeMaxDynamicSharedMemorySize, smA64);

    // char level
    xg_char_kernel<<<dim3(3, 4096), 256, smXC>>>(chars, emb, cWih_f, cWih_b, cbih_f, cbih_b);
    gru_kernel<16,8><<<dim3(2, 512), 384, smG16>>>(cWhh_f, cWhh_b, cbhh_f, cbhh_b, lens, NSEQ_C, T_CH);
    attn_kernel<48><<<NSEQ_C, 512, smA48>>>(wWp, wbp, wctx);
    // message level
    xg_k256_kernel<<<dim3(6, 512), 256, smK>>>(mWih_f, mWih_b, mbih_f, mbih_b);
    gru_kernel<4,4><<<dim3(2, 32), 384, smG4>>>(mWhh_f, mWhh_b, mbhh_f, mbhh_b, nullptr, 128, 64);
    attn_kernel<64><<<128, 512, smA64>>>(pWp, pbp, pctx);
    // head + writeback
    final_kernel<<<128, 256>>>(Wout, bout, (float*)d_out, out_size);
}